// round 2
// baseline (speedup 1.0000x reference)
#include <cuda_runtime.h>

#define Bn 8
#define Cn 12
#define Hn 384
#define Wn 384
#define HWc (Hn*Wn)
#define BHWc (Bn*HWc)
#define LAMf 0.05f
#define EPSf 1e-12f
#define INVN (1.0f/147456.0f)
#define SQ3H 0.86602540378443864676f
#define TWO_PI_D 6.283185307179586476925286766559

// ---------------- scratch (static device allocations; allowed) ----------------
__device__ float2 g_Y[(size_t)Bn*Cn*HWc];   // coil k-space / intermediate, 113 MB
__device__ float2 g_p[BHWc];                // CG search direction (Aop input)
__device__ float2 g_r[BHWc];                // residual
__device__ float2 g_Ap[BHWc];               // Aop(p)
__device__ float  g_rd[Bn], g_rdnew[Bn], g_pAp[Bn];
__device__ float2 g_T[384];                 // e^{-2*pi*i*j/384}

// ---------------- complex helpers ----------------
__device__ __forceinline__ float2 cmul(float2 a, float2 b){
    return make_float2(fmaf(a.x,b.x,-a.y*b.y), fmaf(a.x,b.y, a.y*b.x));
}
__device__ __forceinline__ float2 cadd(float2 a, float2 b){ return make_float2(a.x+b.x, a.y+b.y); }
__device__ __forceinline__ float2 csub(float2 a, float2 b){ return make_float2(a.x-b.x, a.y-b.y); }

template<bool INV>
__device__ __forceinline__ float2 twd(const float2* T, int j){
    float2 w = T[j];                   // (cos, -sin)
    return INV ? make_float2(w.x, -w.y) : w;
}

// ============================================================================
// K1: per (b, 8-row tile): forward row FFT of m_c * p, all 12 coils.
// 512 threads: row r = tid>>6 (8 rows), u = tid&63; each thread does the 3
// sub-FFT butterflies for index u (shared twiddle, 3x ILP).
// Optionally fuses p = r + beta*p.
// smem: V 3072 | M 3072 | A 3072 | B 3072 | T 384  (101376 bytes)
// ============================================================================
template<bool UPD>
__global__ void __launch_bounds__(512,2) k_fwd(const float2* __restrict__ maps){
    extern __shared__ float2 S[];
    float2* V  = S;
    float2* M  = S + 3072;
    float2* A  = S + 6144;
    float2* B2 = S + 9216;
    float2* T  = S + 12288;

    const int tid = threadIdx.x;
    const int row0 = blockIdx.x*8, b = blockIdx.y;
    const int r = tid >> 6, u = tid & 63;
    const int Rb = r*384;
    const int gbase = (b*Hn + row0)*Wn;

    for (int j = tid; j < 384; j += 512) T[j] = g_T[j];

    float beta = 0.f;
    if (UPD) beta = g_rdnew[b] / (g_rd[b] + EPSf);
    for (int idx = tid; idx < 3072; idx += 512){
        float2 v;
        if (UPD){
            float2 rv = g_r[gbase+idx], pv = g_p[gbase+idx];
            v = make_float2(fmaf(beta,pv.x,rv.x), fmaf(beta,pv.y,rv.y));
            g_p[gbase+idx] = v;
        } else {
            v = g_p[gbase+idx];
        }
        V[idx] = v;
    }

    for (int c = 0; c < Cn; c++){
        const float2* mp = maps + ((size_t)(b*Cn + c)*Hn + row0)*Wn;
        for (int idx = tid; idx < 3072; idx += 512) M[idx] = __ldg(&mp[idx]);
        __syncthreads();   // covers V/T (first iter), M, and prev-iter A reads

        // stage 0 (radix-2 on decimated-by-3 input), fused coil multiply
        {
            float2 w = twd<false>(T, 3*u);
            #pragma unroll
            for (int s = 0; s < 3; s++){
                int n0 = s + 3*u;
                float2 a  = cmul(M[Rb+n0],     V[Rb+n0]);
                float2 bb = cmul(M[Rb+n0+192], V[Rb+n0+192]);
                int o = Rb + s*128 + 2*u;
                A[o]   = cadd(a,bb);
                A[o+1] = cmul(csub(a,bb), w);
            }
        }
        __syncthreads();

        float2 *X = A, *Y = B2;
        #pragma unroll
        for (int st = 1; st < 7; st++){
            int q = u & ((1<<st)-1), p = u >> st;
            float2 w = twd<false>(T, p*(3<<st));
            int i0 = q + (p<<st);
            int o0 = q + (p<<(st+1));
            #pragma unroll
            for (int s = 0; s < 3; s++){
                int bs = Rb + s*128;
                float2 a  = X[bs+i0];
                float2 bb = X[bs+i0+64];
                Y[bs+o0]          = cadd(a,bb);
                Y[bs+o0+(1<<st)]  = cmul(csub(a,bb), w);
            }
            float2* t = X; X = Y; Y = t;
            __syncthreads();
        }
        // X == A here (6 swaps). radix-3 combine -> global (natural order)
        float2* yo = g_Y + ((size_t)(b*Cn + c)*Hn + row0)*Wn;
        #pragma unroll
        for (int k = 0; k < 2; k++){
            int item = tid + k*512;
            int rr = item >> 7, k2 = item & 127;
            int bs = rr*384;
            float2 t0 = X[bs+k2];
            float2 t1 = cmul(X[bs+128+k2], twd<false>(T, k2));
            float2 t2 = cmul(X[bs+256+k2], twd<false>(T, 2*k2));
            float2 su = cadd(t1,t2), dv = csub(t1,t2);
            float ex = t0.x - 0.5f*su.x, ey = t0.y - 0.5f*su.y;
            size_t ro = (size_t)rr*Wn;
            yo[ro+k2]     = cadd(t0, su);
            yo[ro+128+k2] = make_float2(ex + SQ3H*dv.y, ey - SQ3H*dv.x);
            yo[ro+256+k2] = make_float2(ex - SQ3H*dv.y, ey + SQ3H*dv.x);
        }
        // next iter's M-load + barrier orders combine(read A) vs stage0(write A)
    }
}

// ============================================================================
// K3: per (b, 8-row tile): inverse row FFT, conj(maps) combine, +lam*p, <p,Ap>
// smem: ACC 3072 | M 3072 | A 3072 | B 3072 | T 384
// ============================================================================
__global__ void __launch_bounds__(512,2) k_inv(const float2* __restrict__ maps){
    extern __shared__ float2 S[];
    float2* ACC = S;
    float2* M   = S + 3072;
    float2* A   = S + 6144;
    float2* B2  = S + 9216;
    float2* T   = S + 12288;
    __shared__ float red[16];

    const int tid = threadIdx.x;
    const int row0 = blockIdx.x*8, b = blockIdx.y;
    const int r = tid >> 6, u = tid & 63;
    const int Rb = r*384;
    const int gbase = (b*Hn + row0)*Wn;

    for (int j = tid; j < 384; j += 512) T[j] = g_T[j];
    for (int idx = tid; idx < 3072; idx += 512) ACC[idx] = make_float2(0.f, 0.f);

    for (int c = 0; c < Cn; c++){
        const size_t cb = ((size_t)(b*Cn + c)*Hn + row0)*Wn;
        const float2* mp = maps + cb;
        for (int idx = tid; idx < 3072; idx += 512){
            M[idx] = __ldg(&mp[idx]);
            A[idx] = g_Y[cb + idx];
        }
        __syncthreads();

        // inverse stage 0
        {
            float2 w = twd<true>(T, 3*u);
            #pragma unroll
            for (int s = 0; s < 3; s++){
                int n0 = s + 3*u;
                float2 a  = A[Rb+n0];
                float2 bb = A[Rb+n0+192];
                int o = Rb + s*128 + 2*u;
                B2[o]   = cadd(a,bb);
                B2[o+1] = cmul(csub(a,bb), w);
            }
        }
        __syncthreads();

        float2 *X = B2, *Y = A;
        #pragma unroll
        for (int st = 1; st < 7; st++){
            int q = u & ((1<<st)-1), p = u >> st;
            float2 w = twd<true>(T, p*(3<<st));
            int i0 = q + (p<<st);
            int o0 = q + (p<<(st+1));
            #pragma unroll
            for (int s = 0; s < 3; s++){
                int bs = Rb + s*128;
                float2 a  = X[bs+i0];
                float2 bb = X[bs+i0+64];
                Y[bs+o0]          = cadd(a,bb);
                Y[bs+o0+(1<<st)]  = cmul(csub(a,bb), w);
            }
            float2* t = X; X = Y; Y = t;
            __syncthreads();
        }
        // X == B2. combine + acc += conj(m)*z
        #pragma unroll
        for (int k = 0; k < 2; k++){
            int item = tid + k*512;
            int rr = item >> 7, k2 = item & 127;
            int bs = rr*384;
            float2 t0 = X[bs+k2];
            float2 t1 = cmul(X[bs+128+k2], twd<true>(T, k2));
            float2 t2 = cmul(X[bs+256+k2], twd<true>(T, 2*k2));
            float2 su = cadd(t1,t2), dv = csub(t1,t2);
            float ex = t0.x - 0.5f*su.x, ey = t0.y - 0.5f*su.y;
            float2 z0 = cadd(t0, su);
            float2 z1 = make_float2(ex - SQ3H*dv.y, ey + SQ3H*dv.x);
            float2 z2 = make_float2(ex + SQ3H*dv.y, ey - SQ3H*dv.x);
            float2 m0 = M[bs+k2], m1 = M[bs+128+k2], m2 = M[bs+256+k2];
            float2 a0 = ACC[bs+k2];
            ACC[bs+k2] = make_float2(fmaf(m0.x,z0.x, fmaf(m0.y,z0.y, a0.x)),
                                     fmaf(m0.x,z0.y, fmaf(-m0.y,z0.x, a0.y)));
            float2 a1 = ACC[bs+128+k2];
            ACC[bs+128+k2] = make_float2(fmaf(m1.x,z1.x, fmaf(m1.y,z1.y, a1.x)),
                                         fmaf(m1.x,z1.y, fmaf(-m1.y,z1.x, a1.y)));
            float2 a2 = ACC[bs+256+k2];
            ACC[bs+256+k2] = make_float2(fmaf(m2.x,z2.x, fmaf(m2.y,z2.y, a2.x)),
                                         fmaf(m2.x,z2.y, fmaf(-m2.y,z2.x, a2.y)));
        }
        // next iter's load + barrier orders ACC/X reads vs overwrites
    }
    __syncthreads();

    // Ap = ACC + lam*p ; accumulate Re<p,Ap>
    float part = 0.f;
    #pragma unroll
    for (int k = 0; k < 6; k++){
        int idx = tid + k*512;
        float2 pv = g_p[gbase+idx];
        float2 o = make_float2(fmaf(LAMf, pv.x, ACC[idx].x), fmaf(LAMf, pv.y, ACC[idx].y));
        g_Ap[gbase+idx] = o;
        part = fmaf(pv.x, o.x, part);
        part = fmaf(pv.y, o.y, part);
    }
    #pragma unroll
    for (int off = 16; off > 0; off >>= 1) part += __shfl_down_sync(0xffffffffu, part, off);
    if ((tid & 31) == 0) red[tid >> 5] = part;
    __syncthreads();
    if (tid == 0){
        float s = 0.f;
        #pragma unroll
        for (int i = 0; i < 16; i++) s += red[i];
        atomicAdd(&g_pAp[b], s);
    }
}

// ============================================================================
// K2: per (b,c,8-col tile): col FFT -> mask*1/N -> col IFFT (unchanged math,
// twiddles moved to smem). smem: A 3072 | B 3072 | T 384 (52224 bytes)
// ============================================================================
template<bool INV>
__device__ __forceinline__ float2* stages512(float2* X, float2* Y, const float2* T, int tid){
    #pragma unroll
    for (int st = 1; st < 7; st++){
        #pragma unroll
        for (int k = 0; k < 3; k++){
            int w   = tid + k*512;
            int col = w & 7;
            int t   = w >> 3;
            int sub = t >> 6, u = t & 63;
            int base = sub*128;
            int q  = u & ((1<<st)-1);
            int p  = u >> st;
            int i0 = base + q + (p<<st);
            float2 a = X[i0*8+col];
            float2 b = X[(i0+64)*8+col];
            float2 tw = twd<INV>(T, p*(3<<st));
            int o0 = base + q + (p<<(st+1));
            Y[o0*8+col]            = cadd(a,b);
            Y[(o0+(1<<st))*8+col]  = cmul(csub(a,b), tw);
        }
        float2* tp = X; X = Y; Y = tp;
        __syncthreads();
    }
    return X;
}

__global__ void __launch_bounds__(512) k_colpass(const float* __restrict__ mask){
    extern __shared__ float2 S[];
    float2* A  = S;
    float2* Bb = S + 3072;
    float2* T  = S + 6144;
    const int tid  = threadIdx.x;
    const int ct   = blockIdx.x, c = blockIdx.y, b = blockIdx.z;
    const int col0 = ct*8;
    const size_t base = (size_t)(b*Cn + c)*HWc;

    for (int j = tid; j < 384; j += 512) T[j] = g_T[j];
    for (int j = tid; j < 3072; j += 512){
        int col = j & 7, h = j >> 3;
        A[j] = g_Y[base + (size_t)h*Wn + col0 + col];
    }
    __syncthreads();

    // forward stage 0
    #pragma unroll
    for (int k = 0; k < 3; k++){
        int w = tid + k*512;
        int col = w & 7; int t = w >> 3;
        int sub = t >> 6, u = t & 63;
        int n0 = sub + 3*u;
        float2 a  = A[n0*8+col];
        float2 b2 = A[(n0+192)*8+col];
        float2 tw = twd<false>(T, 3*u);
        int o = (sub*128 + 2*u)*8 + col;
        Bb[o]   = cadd(a,b2);
        Bb[o+8] = cmul(csub(a,b2), tw);
    }
    __syncthreads();
    float2* F = stages512<false>(Bb, A, T, tid);

    // forward combine fused with mask * 1/N
    #pragma unroll
    for (int k = 0; k < 2; k++){
        int w = tid + k*512;
        int col = w & 7, k2 = w >> 3;
        float2 t0 = F[k2*8+col];
        float2 t1 = cmul(F[(128+k2)*8+col], twd<false>(T, k2));
        float2 t2 = cmul(F[(256+k2)*8+col], twd<false>(T, 2*k2));
        float2 su = cadd(t1,t2), dv = csub(t1,t2);
        float ex = t0.x - 0.5f*su.x, ey = t0.y - 0.5f*su.y;
        const float* mb = mask + b*HWc + col0 + col;
        float s0 = __ldg(&mb[(size_t)k2*Wn])        * INVN;
        float s1 = __ldg(&mb[(size_t)(128+k2)*Wn])  * INVN;
        float s2 = __ldg(&mb[(size_t)(256+k2)*Wn])  * INVN;
        float2 r0 = cadd(t0, su);
        float2 r1 = make_float2(ex + SQ3H*dv.y, ey - SQ3H*dv.x);
        float2 r2 = make_float2(ex - SQ3H*dv.y, ey + SQ3H*dv.x);
        // F==Bb here, write into the other buffer (A)
        A[k2*8+col]        = make_float2(r0.x*s0, r0.y*s0);
        A[(128+k2)*8+col]  = make_float2(r1.x*s1, r1.y*s1);
        A[(256+k2)*8+col]  = make_float2(r2.x*s2, r2.y*s2);
    }
    __syncthreads();

    // inverse stage 0
    #pragma unroll
    for (int k = 0; k < 3; k++){
        int w = tid + k*512;
        int col = w & 7; int t = w >> 3;
        int sub = t >> 6, u = t & 63;
        int n0 = sub + 3*u;
        float2 a  = A[n0*8+col];
        float2 b2 = A[(n0+192)*8+col];
        float2 tw = twd<true>(T, 3*u);
        int o = (sub*128 + 2*u)*8 + col;
        Bb[o]   = cadd(a,b2);
        Bb[o+8] = cmul(csub(a,b2), tw);
    }
    __syncthreads();
    F = stages512<true>(Bb, A, T, tid);

    // inverse combine -> global
    #pragma unroll
    for (int k = 0; k < 2; k++){
        int w = tid + k*512;
        int col = w & 7, k2 = w >> 3;
        float2 t0 = F[k2*8+col];
        float2 t1 = cmul(F[(128+k2)*8+col], twd<true>(T, k2));
        float2 t2 = cmul(F[(256+k2)*8+col], twd<true>(T, 2*k2));
        float2 su = cadd(t1,t2), dv = csub(t1,t2);
        float ex = t0.x - 0.5f*su.x, ey = t0.y - 0.5f*su.y;
        g_Y[base + (size_t)k2*Wn + col0 + col]        = cadd(t0, su);
        g_Y[base + (size_t)(128+k2)*Wn + col0 + col]  = make_float2(ex - SQ3H*dv.y, ey + SQ3H*dv.x);
        g_Y[base + (size_t)(256+k2)*Wn + col0 + col]  = make_float2(ex + SQ3H*dv.y, ey - SQ3H*dv.x);
    }
}

// ---------------- init: rhs = adj + lam*x ; x0=p=rhs ; twiddles; zero scalars ----------------
__global__ void k_init(const float2* __restrict__ x, const float2* __restrict__ adj, float2* __restrict__ xout){
    int idx = blockIdx.y*HWc + blockIdx.x*256 + threadIdx.x;
    float2 xv = x[idx], av = adj[idx];
    float2 rhs = make_float2(fmaf(LAMf, xv.x, av.x), fmaf(LAMf, xv.y, av.y));
    xout[idx] = rhs;
    g_p[idx]  = rhs;
    if (blockIdx.x == 0 && blockIdx.y == 0){
        if (threadIdx.x < Bn){ g_rd[threadIdx.x]=0.f; g_rdnew[threadIdx.x]=0.f; g_pAp[threadIdx.x]=0.f; }
        for (int j = threadIdx.x; j < 384; j += 256){
            double s, c;
            sincos(TWO_PI_D * (double)j / 384.0, &s, &c);
            g_T[j] = make_float2((float)c, (float)(-s));
        }
    }
}

// ---------------- r0: r = rhs - Aop(rhs); p = r; rd = <r,r> ----------------
__global__ void k_r0(const float2* __restrict__ xrhs){
    __shared__ float red[8];
    int b = blockIdx.y;
    int idx = b*HWc + blockIdx.x*256 + threadIdx.x;
    float2 rv = csub(xrhs[idx], g_Ap[idx]);
    g_r[idx] = rv;
    g_p[idx] = rv;
    float part = fmaf(rv.x, rv.x, rv.y*rv.y);
    #pragma unroll
    for (int off = 16; off > 0; off >>= 1) part += __shfl_down_sync(0xffffffffu, part, off);
    if ((threadIdx.x & 31) == 0) red[threadIdx.x >> 5] = part;
    __syncthreads();
    if (threadIdx.x == 0){
        float s = 0.f;
        #pragma unroll
        for (int i = 0; i < 8; i++) s += red[i];
        atomicAdd(&g_rd[b], s);
    }
}

// ---------------- upd1: alpha; x += alpha p; r -= alpha Ap; rdnew = <r,r> ----------------
__global__ void k_upd1(float2* __restrict__ x){
    __shared__ float red[8];
    int b = blockIdx.y;
    int idx = b*HWc + blockIdx.x*256 + threadIdx.x;
    float alpha = g_rd[b] / (g_pAp[b] + EPSf);
    float2 pv = g_p[idx];
    float2 xv = x[idx];
    x[idx] = make_float2(fmaf(alpha, pv.x, xv.x), fmaf(alpha, pv.y, xv.y));
    float2 rv = g_r[idx];
    float2 ap = g_Ap[idx];
    rv = make_float2(fmaf(-alpha, ap.x, rv.x), fmaf(-alpha, ap.y, rv.y));
    g_r[idx] = rv;
    float part = fmaf(rv.x, rv.x, rv.y*rv.y);
    #pragma unroll
    for (int off = 16; off > 0; off >>= 1) part += __shfl_down_sync(0xffffffffu, part, off);
    if ((threadIdx.x & 31) == 0) red[threadIdx.x >> 5] = part;
    __syncthreads();
    if (threadIdx.x == 0){
        float s = 0.f;
        #pragma unroll
        for (int i = 0; i < 8; i++) s += red[i];
        atomicAdd(&g_rdnew[b], s);
    }
}

// ---------------- pre: (optionally) rd <- rdnew ; zero pAp, rdnew ----------------
__global__ void k_pre(int copyrd){
    if (threadIdx.x < Bn){
        if (copyrd) g_rd[threadIdx.x] = g_rdnew[threadIdx.x];
        g_pAp[threadIdx.x]  = 0.f;
        g_rdnew[threadIdx.x] = 0.f;
    }
}

// ---------------- launch ----------------
extern "C" void kernel_launch(void* const* d_in, const int* in_sizes, int n_in,
                              void* d_out, int out_size){
    const float2* x    = (const float2*)d_in[0];
    const float2* adj  = (const float2*)d_in[1];
    const float2* maps = (const float2*)d_in[2];
    const float*  mask = (const float*)d_in[3];
    float2* xout = (float2*)d_out;

    const int SMF = 12672 * sizeof(float2);  // 101376 B for k_fwd / k_inv
    const int SMC = 6528  * sizeof(float2);  // 52224 B for k_colpass
    cudaFuncSetAttribute(k_fwd<false>, cudaFuncAttributeMaxDynamicSharedMemorySize, SMF);
    cudaFuncSetAttribute(k_fwd<true>,  cudaFuncAttributeMaxDynamicSharedMemorySize, SMF);
    cudaFuncSetAttribute(k_inv,        cudaFuncAttributeMaxDynamicSharedMemorySize, SMF);
    cudaFuncSetAttribute(k_colpass,    cudaFuncAttributeMaxDynamicSharedMemorySize, SMC);

    dim3 gElem(HWc/256, Bn);          // 576 x 8, 256 threads
    dim3 gRow(Hn/8, Bn);              // 48 x 8, 512 threads
    dim3 gCol(Wn/8, Cn, Bn);          // 48 x 12 x 8, 512 threads

    k_init<<<gElem, 256>>>(x, adj, xout);

    // r = rhs - Aop(rhs)  (g_p holds rhs)
    k_fwd<false><<<gRow, 512, SMF>>>(maps);
    k_colpass<<<gCol, 512, SMC>>>(mask);
    k_inv<<<gRow, 512, SMF>>>(maps);
    k_r0<<<gElem, 256>>>(xout);

    for (int it = 0; it < 10; ++it){
        if (it) k_fwd<true><<<gRow, 512, SMF>>>(maps);
        else    k_fwd<false><<<gRow, 512, SMF>>>(maps);
        k_pre<<<1, 32>>>(it > 0);
        k_colpass<<<gCol, 512, SMC>>>(mask);
        k_inv<<<gRow, 512, SMF>>>(maps);
        k_upd1<<<gElem, 256>>>(xout);
    }
}

// round 3
// speedup vs baseline: 1.5769x; 1.5769x over previous
#include <cuda_runtime.h>

#define Bn 8
#define Cn 12
#define Hn 384
#define Wn 384
#define HWc (Hn*Wn)
#define BHWc (Bn*HWc)
#define LAMf 0.05f
#define EPSf 1e-12f
#define INVN (1.0f/147456.0f)
#define SQ3H 0.86602540378443864676f
#define TWO_PI_D 6.283185307179586476925286766559

// ---------------- scratch (static device arrays; allowed) ----------------
__device__ float2 g_Y[(size_t)Bn*Cn*HWc];   // coil k-space, 113 MB
__device__ float2 g_p[BHWc];
__device__ float2 g_r[BHWc];
__device__ float2 g_Ap[BHWc];
__device__ float  g_rd[Bn], g_rdnew[Bn], g_pAp[Bn];
__device__ float2 g_T[384];                 // W_384^j = (cos, -sin)

// ---------------- complex helpers ----------------
__device__ __forceinline__ float2 cmul(float2 a, float2 b){
    return make_float2(fmaf(a.x,b.x,-a.y*b.y), fmaf(a.x,b.y, a.y*b.x));
}
__device__ __forceinline__ float2 cadd(float2 a, float2 b){ return make_float2(a.x+b.x, a.y+b.y); }
__device__ __forceinline__ float2 csub(float2 a, float2 b){ return make_float2(a.x-b.x, a.y-b.y); }
__device__ __forceinline__ unsigned br5(unsigned x){ return __brev(x) >> 27; }

// ---------------- FFT-12 in registers, natural in/out, unnormalized -------
template<bool INV>
__device__ __forceinline__ void fft12(float2* v){
    float2 F0[4], F1[4], F2[4];
    // three FFT-4s over n = 3n'+r
    {
        float2 x0=v[0], x1=v[3], x2=v[6], x3=v[9];
        float2 t0=cadd(x0,x2), t1=csub(x0,x2), t2=cadd(x1,x3), t3=csub(x1,x3);
        F0[0]=cadd(t0,t2); F0[2]=csub(t0,t2);
        if(!INV){ F0[1]=make_float2(t1.x+t3.y, t1.y-t3.x); F0[3]=make_float2(t1.x-t3.y, t1.y+t3.x); }
        else    { F0[1]=make_float2(t1.x-t3.y, t1.y+t3.x); F0[3]=make_float2(t1.x+t3.y, t1.y-t3.x); }
    }
    {
        float2 x0=v[1], x1=v[4], x2=v[7], x3=v[10];
        float2 t0=cadd(x0,x2), t1=csub(x0,x2), t2=cadd(x1,x3), t3=csub(x1,x3);
        F1[0]=cadd(t0,t2); F1[2]=csub(t0,t2);
        if(!INV){ F1[1]=make_float2(t1.x+t3.y, t1.y-t3.x); F1[3]=make_float2(t1.x-t3.y, t1.y+t3.x); }
        else    { F1[1]=make_float2(t1.x-t3.y, t1.y+t3.x); F1[3]=make_float2(t1.x+t3.y, t1.y-t3.x); }
    }
    {
        float2 x0=v[2], x1=v[5], x2=v[8], x3=v[11];
        float2 t0=cadd(x0,x2), t1=csub(x0,x2), t2=cadd(x1,x3), t3=csub(x1,x3);
        F2[0]=cadd(t0,t2); F2[2]=csub(t0,t2);
        if(!INV){ F2[1]=make_float2(t1.x+t3.y, t1.y-t3.x); F2[3]=make_float2(t1.x-t3.y, t1.y+t3.x); }
        else    { F2[1]=make_float2(t1.x-t3.y, t1.y+t3.x); F2[3]=make_float2(t1.x+t3.y, t1.y-t3.x); }
    }
    // twiddles W12^{r*k4} (conjugate for INV)
    const float c1 = SQ3H, s1 = 0.5f;
    const float sg = INV ? -1.f : 1.f;
    F1[1] = cmul(F1[1], make_float2(c1, -sg*s1));
    F2[1] = cmul(F2[1], make_float2(s1, -sg*c1));
    F1[2] = cmul(F1[2], make_float2(s1, -sg*c1));
    F2[2] = cmul(F2[2], make_float2(-s1, -sg*c1));
    F1[3] = INV ? make_float2(-F1[3].y, F1[3].x) : make_float2(F1[3].y, -F1[3].x);
    F2[3] = make_float2(-F2[3].x, -F2[3].y);
    // DFT-3 over r for each k4
    #pragma unroll
    for (int k4 = 0; k4 < 4; k4++){
        float2 a=F0[k4], b=F1[k4], c=F2[k4];
        float2 s=cadd(b,c), d=csub(b,c);
        v[k4] = cadd(a, s);
        float ex = a.x - 0.5f*s.x, ey = a.y - 0.5f*s.y;
        if(!INV){
            v[k4+4] = make_float2(ex + SQ3H*d.y, ey - SQ3H*d.x);
            v[k4+8] = make_float2(ex - SQ3H*d.y, ey + SQ3H*d.x);
        } else {
            v[k4+4] = make_float2(ex - SQ3H*d.y, ey + SQ3H*d.x);
            v[k4+8] = make_float2(ex + SQ3H*d.y, ey - SQ3H*d.x);
        }
    }
}

// ---------------- FFT-32 across lanes (12 independent values per lane) ----
// Forward: DIF, natural input -> bit-reversed output (lane l holds X[br5(l)]).
// Inverse: DIT with conjugate twiddles, bit-reversed input -> natural output.
// tw[0..3] = W_32^{(l&15)}, W_32^{2(l&7)}, W_32^{4(l&3)}, W_32^{8(l&1)}
__device__ __forceinline__ void fft32_fwd(float2* v, const float2* tw, unsigned lane){
    #pragma unroll
    for (int s = 0; s < 5; s++){
        const int h = 16 >> s;
        const bool up = (lane & h) != 0;
        #pragma unroll
        for (int j = 0; j < 12; j++){
            float2 t;
            t.x = __shfl_xor_sync(0xffffffffu, v[j].x, h);
            t.y = __shfl_xor_sync(0xffffffffu, v[j].y, h);
            float2 nv = up ? csub(t, v[j]) : cadd(v[j], t);
            if (s < 4 && up) nv = cmul(nv, tw[s]);
            v[j] = nv;
        }
    }
}
__device__ __forceinline__ void fft32_inv(float2* v, const float2* tw, unsigned lane){
    #pragma unroll
    for (int s = 0; s < 5; s++){
        const int h = 1 << s;
        const bool up = (lane & h) != 0;
        #pragma unroll
        for (int j = 0; j < 12; j++){
            float2 vv = v[j];
            if (s > 0 && up){
                float2 w = tw[4 - s];
                vv = cmul(vv, make_float2(w.x, -w.y));
            }
            float2 t;
            t.x = __shfl_xor_sync(0xffffffffu, vv.x, h);
            t.y = __shfl_xor_sync(0xffffffffu, vv.y, h);
            v[j] = up ? csub(t, vv) : cadd(vv, t);
        }
    }
}

// load per-lane twiddles from the 3KB table
__device__ __forceinline__ void load_tw(unsigned lane, float2* t12, float2* tw32){
    #pragma unroll
    for (int j = 0; j < 12; j++) t12[j] = __ldg(&g_T[lane*j]);   // lane*j <= 341
    tw32[0] = __ldg(&g_T[(lane & 15) * 12]);
    tw32[1] = __ldg(&g_T[((lane & 7) * 2) * 12]);
    tw32[2] = __ldg(&g_T[((lane & 3) * 4) * 12]);
    tw32[3] = __ldg(&g_T[((lane & 1) * 8) * 12]);
}

// ============================================================================
// K1: warp per (b,row): fwd row FFT of m_c*p for all 12 coils.
// Optionally fuses p = r + beta*p. No __syncthreads.
// ============================================================================
template<bool UPD>
__global__ void __launch_bounds__(256,2) k_fwd(const float2* __restrict__ maps){
    const unsigned lane = threadIdx.x & 31;
    const int wid = threadIdx.x >> 5;
    const int row = blockIdx.x*8 + wid;
    const int b   = blockIdx.y;

    float2 t12[12], tw32[4];
    load_tw(lane, t12, tw32);

    const int gbase = (b*Hn + row)*Wn;
    float2 V[12];
    float beta = 0.f;
    if (UPD) beta = g_rdnew[b] / (g_rd[b] + EPSf);
    #pragma unroll
    for (int j = 0; j < 12; j++){
        int idx = gbase + (int)lane + 32*j;
        if (UPD){
            float2 rv = g_r[idx], pv = g_p[idx];
            V[j] = make_float2(fmaf(beta, pv.x, rv.x), fmaf(beta, pv.y, rv.y));
            g_p[idx] = V[j];
        } else {
            V[j] = g_p[idx];
        }
    }

    for (int c = 0; c < Cn; c++){
        const float2* mp = maps + ((size_t)(b*Cn + c)*Hn + row)*Wn;
        float2 X[12];
        #pragma unroll
        for (int j = 0; j < 12; j++) X[j] = cmul(__ldg(mp + lane + 32*j), V[j]);
        fft12<false>(X);
        #pragma unroll
        for (int j = 1; j < 12; j++) X[j] = cmul(X[j], t12[j]);
        fft32_fwd(X, tw32, lane);
        float2* yo = g_Y + ((size_t)(b*Cn + c)*Hn + row)*Wn;
        #pragma unroll
        for (int j = 0; j < 12; j++) yo[lane + 32*j] = X[j];
    }
}

// ============================================================================
// K2: block = 8 columns of one (b,c): col FFT -> mask*INVN -> col IFFT.
// Warp per column; smem only as gmem<->warp transpose staging (2 syncthreads).
// ============================================================================
__global__ void __launch_bounds__(256,2) k_col(const float* __restrict__ mask){
    __shared__ float2 S[384*9];
    const unsigned lane = threadIdx.x & 31;
    const int wid = threadIdx.x >> 5;
    const int tid = threadIdx.x;
    const int p0 = blockIdx.x*8, c = blockIdx.y, b = blockIdx.z;
    const size_t base = (size_t)(b*Cn + c)*HWc;

    float2 t12[12], tw32[4];
    load_tw(lane, t12, tw32);

    // mask prefetch for this warp's column (stored position p -> true kx)
    const int p  = p0 + wid;
    const int kx = (p >> 5) + 12*(int)br5((unsigned)(p & 31));
    const unsigned rl = br5(lane);
    float msk[12];
    const float* mrow = mask + (size_t)b*HWc + kx;
    #pragma unroll
    for (int j = 0; j < 12; j++) msk[j] = __ldg(mrow + ((size_t)j + 12*rl)*Wn) * INVN;

    // coalesced tile load: 384 h x 8 cols
    #pragma unroll
    for (int k = 0; k < 12; k++){
        int idx = tid + k*256;
        int pc = idx & 7, h = idx >> 3;
        S[h*9 + pc] = g_Y[base + (size_t)h*Wn + p0 + pc];
    }
    __syncthreads();

    float2 X[12];
    #pragma unroll
    for (int j = 0; j < 12; j++) X[j] = S[(lane + 32*j)*9 + wid];

    fft12<false>(X);
    #pragma unroll
    for (int j = 1; j < 12; j++) X[j] = cmul(X[j], t12[j]);
    fft32_fwd(X, tw32, lane);

    #pragma unroll
    for (int j = 0; j < 12; j++) X[j] = make_float2(X[j].x*msk[j], X[j].y*msk[j]);

    fft32_inv(X, tw32, lane);
    #pragma unroll
    for (int j = 1; j < 12; j++) X[j] = cmul(X[j], make_float2(t12[j].x, -t12[j].y));
    fft12<true>(X);

    #pragma unroll
    for (int j = 0; j < 12; j++) S[(lane + 32*j)*9 + wid] = X[j];
    __syncthreads();

    #pragma unroll
    for (int k = 0; k < 12; k++){
        int idx = tid + k*256;
        int pc = idx & 7, h = idx >> 3;
        g_Y[base + (size_t)h*Wn + p0 + pc] = S[h*9 + pc];
    }
}

// ============================================================================
// K3: warp per (b,row): inv row FFT per coil, acc += conj(m)*z, Ap = acc+lam*p,
// block-reduced Re<p,Ap> -> atomicAdd. One __syncthreads for the reduction.
// ============================================================================
__global__ void __launch_bounds__(256,2) k_inv(const float2* __restrict__ maps){
    __shared__ float red[8];
    const unsigned lane = threadIdx.x & 31;
    const int wid = threadIdx.x >> 5;
    const int row = blockIdx.x*8 + wid;
    const int b   = blockIdx.y;

    float2 t12[12], tw32[4];
    load_tw(lane, t12, tw32);

    float2 acc[12];
    #pragma unroll
    for (int j = 0; j < 12; j++) acc[j] = make_float2(0.f, 0.f);

    for (int c = 0; c < Cn; c++){
        const size_t cb = ((size_t)(b*Cn + c)*Hn + row)*Wn;
        float2 X[12];
        #pragma unroll
        for (int j = 0; j < 12; j++) X[j] = g_Y[cb + lane + 32*j];
        fft32_inv(X, tw32, lane);
        #pragma unroll
        for (int j = 1; j < 12; j++) X[j] = cmul(X[j], make_float2(t12[j].x, -t12[j].y));
        fft12<true>(X);
        const float2* mp = maps + cb;
        #pragma unroll
        for (int j = 0; j < 12; j++){
            float2 m = __ldg(mp + lane + 32*j);
            float2 z = X[j];
            acc[j].x = fmaf(m.x, z.x, fmaf(m.y, z.y, acc[j].x));
            acc[j].y = fmaf(m.x, z.y, fmaf(-m.y, z.x, acc[j].y));
        }
    }

    const int gbase = (b*Hn + row)*Wn;
    float part = 0.f;
    #pragma unroll
    for (int j = 0; j < 12; j++){
        int idx = gbase + (int)lane + 32*j;
        float2 pv = g_p[idx];
        float2 o = make_float2(fmaf(LAMf, pv.x, acc[j].x), fmaf(LAMf, pv.y, acc[j].y));
        g_Ap[idx] = o;
        part = fmaf(pv.x, o.x, part);
        part = fmaf(pv.y, o.y, part);
    }
    #pragma unroll
    for (int off = 16; off > 0; off >>= 1) part += __shfl_down_sync(0xffffffffu, part, off);
    if (lane == 0) red[wid] = part;
    __syncthreads();
    if (threadIdx.x == 0){
        float s = 0.f;
        #pragma unroll
        for (int i = 0; i < 8; i++) s += red[i];
        atomicAdd(&g_pAp[b], s);
    }
}

// ---------------- init: rhs = adj + lam*x ; x0=p=rhs ; twiddles; scalars ----
__global__ void k_init(const float2* __restrict__ x, const float2* __restrict__ adj, float2* __restrict__ xout){
    int idx = blockIdx.y*HWc + blockIdx.x*256 + threadIdx.x;
    float2 xv = x[idx], av = adj[idx];
    float2 rhs = make_float2(fmaf(LAMf, xv.x, av.x), fmaf(LAMf, xv.y, av.y));
    xout[idx] = rhs;
    g_p[idx]  = rhs;
    if (blockIdx.x == 0 && blockIdx.y == 0){
        if (threadIdx.x < Bn){ g_rd[threadIdx.x]=0.f; g_rdnew[threadIdx.x]=0.f; g_pAp[threadIdx.x]=0.f; }
        for (int j = threadIdx.x; j < 384; j += 256){
            double s, c;
            sincos(TWO_PI_D * (double)j / 384.0, &s, &c);
            g_T[j] = make_float2((float)c, (float)(-s));
        }
    }
}

// ---------------- r0: r = rhs - Aop(rhs); p = r; rd = <r,r> ----------------
__global__ void k_r0(const float2* __restrict__ xrhs){
    __shared__ float red[8];
    int b = blockIdx.y;
    int idx = b*HWc + blockIdx.x*256 + threadIdx.x;
    float2 rv = csub(xrhs[idx], g_Ap[idx]);
    g_r[idx] = rv;
    g_p[idx] = rv;
    float part = fmaf(rv.x, rv.x, rv.y*rv.y);
    #pragma unroll
    for (int off = 16; off > 0; off >>= 1) part += __shfl_down_sync(0xffffffffu, part, off);
    if ((threadIdx.x & 31) == 0) red[threadIdx.x >> 5] = part;
    __syncthreads();
    if (threadIdx.x == 0){
        float s = 0.f;
        #pragma unroll
        for (int i = 0; i < 8; i++) s += red[i];
        atomicAdd(&g_rd[b], s);
    }
}

// ---------------- upd1: alpha; x += alpha p; r -= alpha Ap; rdnew=<r,r> ----
__global__ void k_upd1(float2* __restrict__ x){
    __shared__ float red[8];
    int b = blockIdx.y;
    int idx = b*HWc + blockIdx.x*256 + threadIdx.x;
    float alpha = g_rd[b] / (g_pAp[b] + EPSf);
    float2 pv = g_p[idx];
    float2 xv = x[idx];
    x[idx] = make_float2(fmaf(alpha, pv.x, xv.x), fmaf(alpha, pv.y, xv.y));
    float2 rv = g_r[idx];
    float2 ap = g_Ap[idx];
    rv = make_float2(fmaf(-alpha, ap.x, rv.x), fmaf(-alpha, ap.y, rv.y));
    g_r[idx] = rv;
    float part = fmaf(rv.x, rv.x, rv.y*rv.y);
    #pragma unroll
    for (int off = 16; off > 0; off >>= 1) part += __shfl_down_sync(0xffffffffu, part, off);
    if ((threadIdx.x & 31) == 0) red[threadIdx.x >> 5] = part;
    __syncthreads();
    if (threadIdx.x == 0){
        float s = 0.f;
        #pragma unroll
        for (int i = 0; i < 8; i++) s += red[i];
        atomicAdd(&g_rdnew[b], s);
    }
}

// ---------------- pre: (optionally) rd <- rdnew ; zero pAp, rdnew ----------
__global__ void k_pre(int copyrd){
    if (threadIdx.x < Bn){
        if (copyrd) g_rd[threadIdx.x] = g_rdnew[threadIdx.x];
        g_pAp[threadIdx.x]  = 0.f;
        g_rdnew[threadIdx.x] = 0.f;
    }
}

// ---------------- launch ----------------
extern "C" void kernel_launch(void* const* d_in, const int* in_sizes, int n_in,
                              void* d_out, int out_size){
    const float2* x    = (const float2*)d_in[0];
    const float2* adj  = (const float2*)d_in[1];
    const float2* maps = (const float2*)d_in[2];
    const float*  mask = (const float*)d_in[3];
    float2* xout = (float2*)d_out;

    dim3 gElem(HWc/256, Bn);      // 576 x 8
    dim3 gRow(Hn/8, Bn);          // 48 x 8, 256 thr (8 warps = 8 rows)
    dim3 gCol(Wn/8, Cn, Bn);      // 48 x 12 x 8, 256 thr (8 warps = 8 cols)

    k_init<<<gElem, 256>>>(x, adj, xout);

    // r = rhs - Aop(rhs)  (g_p holds rhs)
    k_fwd<false><<<gRow, 256>>>(maps);
    k_col<<<gCol, 256>>>(mask);
    k_inv<<<gRow, 256>>>(maps);
    k_r0<<<gElem, 256>>>(xout);

    for (int it = 0; it < 10; ++it){
        if (it) k_fwd<true><<<gRow, 256>>>(maps);
        else    k_fwd<false><<<gRow, 256>>>(maps);
        k_pre<<<1, 32>>>(it > 0);
        k_col<<<gCol, 256>>>(mask);
        k_inv<<<gRow, 256>>>(maps);
        k_upd1<<<gElem, 256>>>(xout);
    }
}

// round 4
// speedup vs baseline: 1.6712x; 1.0598x over previous
#include <cuda_runtime.h>
#include <cuda_fp16.h>

#define Bn 8
#define Cn 12
#define Hn 384
#define Wn 384
#define HWc (Hn*Wn)
#define BHWc (Bn*HWc)
#define LAMf 0.05f
#define EPSf 1e-12f
#define INVN (1.0f/147456.0f)
#define SQ3H 0.86602540378443864676f
#define TWO_PI_D 6.283185307179586476925286766559

// ---------------- scratch (static device arrays; allowed) ----------------
__device__ __half2 g_Y[(size_t)Bn*Cn*HWc]; // coil k-space, fp16, 56.6 MB (L2-resident)
__device__ float2 g_p[BHWc];
__device__ float2 g_r[BHWc];
__device__ float2 g_Ap[BHWc];
__device__ float  g_rd[Bn], g_rdnew[Bn], g_pAp[Bn];
__device__ float2 g_T[384];                 // W_384^j = (cos, -sin)

// ---------------- complex helpers ----------------
__device__ __forceinline__ float2 cmul(float2 a, float2 b){
    return make_float2(fmaf(a.x,b.x,-a.y*b.y), fmaf(a.x,b.y, a.y*b.x));
}
__device__ __forceinline__ float2 cadd(float2 a, float2 b){ return make_float2(a.x+b.x, a.y+b.y); }
__device__ __forceinline__ float2 csub(float2 a, float2 b){ return make_float2(a.x-b.x, a.y-b.y); }
__device__ __forceinline__ unsigned br5(unsigned x){ return __brev(x) >> 27; }
__device__ __forceinline__ __half2 c2h(float2 v){ return __floats2half2_rn(v.x, v.y); }
__device__ __forceinline__ float2 h2c(__half2 h){ return __half22float2(h); }

// ---------------- FFT-12 in registers, natural in/out, unnormalized -------
template<bool INV>
__device__ __forceinline__ void fft12(float2* v){
    float2 F0[4], F1[4], F2[4];
    {
        float2 x0=v[0], x1=v[3], x2=v[6], x3=v[9];
        float2 t0=cadd(x0,x2), t1=csub(x0,x2), t2=cadd(x1,x3), t3=csub(x1,x3);
        F0[0]=cadd(t0,t2); F0[2]=csub(t0,t2);
        if(!INV){ F0[1]=make_float2(t1.x+t3.y, t1.y-t3.x); F0[3]=make_float2(t1.x-t3.y, t1.y+t3.x); }
        else    { F0[1]=make_float2(t1.x-t3.y, t1.y+t3.x); F0[3]=make_float2(t1.x+t3.y, t1.y-t3.x); }
    }
    {
        float2 x0=v[1], x1=v[4], x2=v[7], x3=v[10];
        float2 t0=cadd(x0,x2), t1=csub(x0,x2), t2=cadd(x1,x3), t3=csub(x1,x3);
        F1[0]=cadd(t0,t2); F1[2]=csub(t0,t2);
        if(!INV){ F1[1]=make_float2(t1.x+t3.y, t1.y-t3.x); F1[3]=make_float2(t1.x-t3.y, t1.y+t3.x); }
        else    { F1[1]=make_float2(t1.x-t3.y, t1.y+t3.x); F1[3]=make_float2(t1.x+t3.y, t1.y-t3.x); }
    }
    {
        float2 x0=v[2], x1=v[5], x2=v[8], x3=v[11];
        float2 t0=cadd(x0,x2), t1=csub(x0,x2), t2=cadd(x1,x3), t3=csub(x1,x3);
        F2[0]=cadd(t0,t2); F2[2]=csub(t0,t2);
        if(!INV){ F2[1]=make_float2(t1.x+t3.y, t1.y-t3.x); F2[3]=make_float2(t1.x-t3.y, t1.y+t3.x); }
        else    { F2[1]=make_float2(t1.x-t3.y, t1.y+t3.x); F2[3]=make_float2(t1.x+t3.y, t1.y-t3.x); }
    }
    const float c1 = SQ3H, s1 = 0.5f;
    const float sg = INV ? -1.f : 1.f;
    F1[1] = cmul(F1[1], make_float2(c1, -sg*s1));
    F2[1] = cmul(F2[1], make_float2(s1, -sg*c1));
    F1[2] = cmul(F1[2], make_float2(s1, -sg*c1));
    F2[2] = cmul(F2[2], make_float2(-s1, -sg*c1));
    F1[3] = INV ? make_float2(-F1[3].y, F1[3].x) : make_float2(F1[3].y, -F1[3].x);
    F2[3] = make_float2(-F2[3].x, -F2[3].y);
    #pragma unroll
    for (int k4 = 0; k4 < 4; k4++){
        float2 a=F0[k4], b=F1[k4], c=F2[k4];
        float2 s=cadd(b,c), d=csub(b,c);
        v[k4] = cadd(a, s);
        float ex = a.x - 0.5f*s.x, ey = a.y - 0.5f*s.y;
        if(!INV){
            v[k4+4] = make_float2(ex + SQ3H*d.y, ey - SQ3H*d.x);
            v[k4+8] = make_float2(ex - SQ3H*d.y, ey + SQ3H*d.x);
        } else {
            v[k4+4] = make_float2(ex - SQ3H*d.y, ey + SQ3H*d.x);
            v[k4+8] = make_float2(ex + SQ3H*d.y, ey - SQ3H*d.x);
        }
    }
}

// ---------------- FFT-32 across lanes ----------------
__device__ __forceinline__ void fft32_fwd(float2* v, const float2* tw, unsigned lane){
    #pragma unroll
    for (int s = 0; s < 5; s++){
        const int h = 16 >> s;
        const bool up = (lane & h) != 0;
        #pragma unroll
        for (int j = 0; j < 12; j++){
            float2 t;
            t.x = __shfl_xor_sync(0xffffffffu, v[j].x, h);
            t.y = __shfl_xor_sync(0xffffffffu, v[j].y, h);
            float2 nv = up ? csub(t, v[j]) : cadd(v[j], t);
            if (s < 4 && up) nv = cmul(nv, tw[s]);
            v[j] = nv;
        }
    }
}
__device__ __forceinline__ void fft32_inv(float2* v, const float2* tw, unsigned lane){
    #pragma unroll
    for (int s = 0; s < 5; s++){
        const int h = 1 << s;
        const bool up = (lane & h) != 0;
        #pragma unroll
        for (int j = 0; j < 12; j++){
            float2 vv = v[j];
            if (s > 0 && up){
                float2 w = tw[4 - s];
                vv = cmul(vv, make_float2(w.x, -w.y));
            }
            float2 t;
            t.x = __shfl_xor_sync(0xffffffffu, vv.x, h);
            t.y = __shfl_xor_sync(0xffffffffu, vv.y, h);
            v[j] = up ? csub(t, vv) : cadd(vv, t);
        }
    }
}

__device__ __forceinline__ void load_tw(unsigned lane, float2* t12, float2* tw32){
    #pragma unroll
    for (int j = 0; j < 12; j++) t12[j] = __ldg(&g_T[lane*j]);
    tw32[0] = __ldg(&g_T[(lane & 15) * 12]);
    tw32[1] = __ldg(&g_T[((lane & 7) * 2) * 12]);
    tw32[2] = __ldg(&g_T[((lane & 3) * 4) * 12]);
    tw32[3] = __ldg(&g_T[((lane & 1) * 8) * 12]);
}

// ============================================================================
// K1: warp per (b,row): fwd row FFT of m_c*p for all 12 coils. Y out in fp16.
// ============================================================================
template<bool UPD>
__global__ void __launch_bounds__(256,2) k_fwd(const float2* __restrict__ maps){
    const unsigned lane = threadIdx.x & 31;
    const int wid = threadIdx.x >> 5;
    const int row = blockIdx.x*8 + wid;
    const int b   = blockIdx.y;

    float2 t12[12], tw32[4];
    load_tw(lane, t12, tw32);

    const int gbase = (b*Hn + row)*Wn;
    float2 V[12];
    float beta = 0.f;
    if (UPD) beta = g_rdnew[b] / (g_rd[b] + EPSf);
    #pragma unroll
    for (int j = 0; j < 12; j++){
        int idx = gbase + (int)lane + 32*j;
        if (UPD){
            float2 rv = g_r[idx], pv = g_p[idx];
            V[j] = make_float2(fmaf(beta, pv.x, rv.x), fmaf(beta, pv.y, rv.y));
            g_p[idx] = V[j];
        } else {
            V[j] = g_p[idx];
        }
    }

    for (int c = 0; c < Cn; c++){
        const float2* mp = maps + ((size_t)(b*Cn + c)*Hn + row)*Wn;
        float2 X[12];
        #pragma unroll
        for (int j = 0; j < 12; j++) X[j] = cmul(__ldg(mp + lane + 32*j), V[j]);
        fft12<false>(X);
        #pragma unroll
        for (int j = 1; j < 12; j++) X[j] = cmul(X[j], t12[j]);
        fft32_fwd(X, tw32, lane);
        __half2* yo = g_Y + ((size_t)(b*Cn + c)*Hn + row)*Wn;
        #pragma unroll
        for (int j = 0; j < 12; j++) yo[lane + 32*j] = c2h(X[j]);
    }
}

// ============================================================================
// K2: block = 8 columns of one (b,c): col FFT -> mask*INVN -> col IFFT.
// ============================================================================
__global__ void __launch_bounds__(256,2) k_col(const float* __restrict__ mask){
    __shared__ __half2 S[384*9];
    const unsigned lane = threadIdx.x & 31;
    const int wid = threadIdx.x >> 5;
    const int tid = threadIdx.x;
    const int p0 = blockIdx.x*8, c = blockIdx.y, b = blockIdx.z;
    const size_t base = (size_t)(b*Cn + c)*HWc;

    float2 t12[12], tw32[4];
    load_tw(lane, t12, tw32);

    // mask for this warp's column (stored position p -> true kx)
    const int p  = p0 + wid;
    const int kx = (p >> 5) + 12*(int)br5((unsigned)(p & 31));
    const unsigned rl = br5(lane);
    float msk[12];
    const float* mrow = mask + (size_t)b*HWc + kx;
    #pragma unroll
    for (int j = 0; j < 12; j++) msk[j] = __ldg(mrow + ((size_t)j + 12*rl)*Wn) * INVN;

    // coalesced tile load: 384 h x 8 cols
    #pragma unroll
    for (int k = 0; k < 12; k++){
        int idx = tid + k*256;
        int pc = idx & 7, h = idx >> 3;
        S[h*9 + pc] = g_Y[base + (size_t)h*Wn + p0 + pc];
    }
    __syncthreads();

    float2 X[12];
    #pragma unroll
    for (int j = 0; j < 12; j++) X[j] = h2c(S[(lane + 32*j)*9 + wid]);

    fft12<false>(X);
    #pragma unroll
    for (int j = 1; j < 12; j++) X[j] = cmul(X[j], t12[j]);
    fft32_fwd(X, tw32, lane);

    #pragma unroll
    for (int j = 0; j < 12; j++) X[j] = make_float2(X[j].x*msk[j], X[j].y*msk[j]);

    fft32_inv(X, tw32, lane);
    #pragma unroll
    for (int j = 1; j < 12; j++) X[j] = cmul(X[j], make_float2(t12[j].x, -t12[j].y));
    fft12<true>(X);

    #pragma unroll
    for (int j = 0; j < 12; j++) S[(lane + 32*j)*9 + wid] = c2h(X[j]);
    __syncthreads();

    #pragma unroll
    for (int k = 0; k < 12; k++){
        int idx = tid + k*256;
        int pc = idx & 7, h = idx >> 3;
        g_Y[base + (size_t)h*Wn + p0 + pc] = S[h*9 + pc];
    }
}

// ============================================================================
// K3: warp per (b,row): inv row FFT per coil, acc += conj(m)*z, Ap = acc+lam*p
// ============================================================================
__global__ void __launch_bounds__(256,2) k_inv(const float2* __restrict__ maps){
    __shared__ float red[8];
    const unsigned lane = threadIdx.x & 31;
    const int wid = threadIdx.x >> 5;
    const int row = blockIdx.x*8 + wid;
    const int b   = blockIdx.y;

    float2 t12[12], tw32[4];
    load_tw(lane, t12, tw32);

    float2 acc[12];
    #pragma unroll
    for (int j = 0; j < 12; j++) acc[j] = make_float2(0.f, 0.f);

    for (int c = 0; c < Cn; c++){
        const size_t cb = ((size_t)(b*Cn + c)*Hn + row)*Wn;
        float2 X[12];
        #pragma unroll
        for (int j = 0; j < 12; j++) X[j] = h2c(g_Y[cb + lane + 32*j]);
        fft32_inv(X, tw32, lane);
        #pragma unroll
        for (int j = 1; j < 12; j++) X[j] = cmul(X[j], make_float2(t12[j].x, -t12[j].y));
        fft12<true>(X);
        const float2* mp = maps + cb;
        #pragma unroll
        for (int j = 0; j < 12; j++){
            float2 m = __ldg(mp + lane + 32*j);
            float2 z = X[j];
            acc[j].x = fmaf(m.x, z.x, fmaf(m.y, z.y, acc[j].x));
            acc[j].y = fmaf(m.x, z.y, fmaf(-m.y, z.x, acc[j].y));
        }
    }

    const int gbase = (b*Hn + row)*Wn;
    float part = 0.f;
    #pragma unroll
    for (int j = 0; j < 12; j++){
        int idx = gbase + (int)lane + 32*j;
        float2 pv = g_p[idx];
        float2 o = make_float2(fmaf(LAMf, pv.x, acc[j].x), fmaf(LAMf, pv.y, acc[j].y));
        g_Ap[idx] = o;
        part = fmaf(pv.x, o.x, part);
        part = fmaf(pv.y, o.y, part);
    }
    #pragma unroll
    for (int off = 16; off > 0; off >>= 1) part += __shfl_down_sync(0xffffffffu, part, off);
    if (lane == 0) red[wid] = part;
    __syncthreads();
    if (threadIdx.x == 0){
        float s = 0.f;
        #pragma unroll
        for (int i = 0; i < 8; i++) s += red[i];
        atomicAdd(&g_pAp[b], s);
    }
}

// ---------------- init ----------------
__global__ void k_init(const float2* __restrict__ x, const float2* __restrict__ adj, float2* __restrict__ xout){
    int idx = blockIdx.y*HWc + blockIdx.x*256 + threadIdx.x;
    float2 xv = x[idx], av = adj[idx];
    float2 rhs = make_float2(fmaf(LAMf, xv.x, av.x), fmaf(LAMf, xv.y, av.y));
    xout[idx] = rhs;
    g_p[idx]  = rhs;
    if (blockIdx.x == 0 && blockIdx.y == 0){
        if (threadIdx.x < Bn){ g_rd[threadIdx.x]=0.f; g_rdnew[threadIdx.x]=0.f; g_pAp[threadIdx.x]=0.f; }
        for (int j = threadIdx.x; j < 384; j += 256){
            double s, c;
            sincos(TWO_PI_D * (double)j / 384.0, &s, &c);
            g_T[j] = make_float2((float)c, (float)(-s));
        }
    }
}

// ---------------- r0 ----------------
__global__ void k_r0(const float2* __restrict__ xrhs){
    __shared__ float red[8];
    int b = blockIdx.y;
    int idx = b*HWc + blockIdx.x*256 + threadIdx.x;
    float2 rv = csub(xrhs[idx], g_Ap[idx]);
    g_r[idx] = rv;
    g_p[idx] = rv;
    float part = fmaf(rv.x, rv.x, rv.y*rv.y);
    #pragma unroll
    for (int off = 16; off > 0; off >>= 1) part += __shfl_down_sync(0xffffffffu, part, off);
    if ((threadIdx.x & 31) == 0) red[threadIdx.x >> 5] = part;
    __syncthreads();
    if (threadIdx.x == 0){
        float s = 0.f;
        #pragma unroll
        for (int i = 0; i < 8; i++) s += red[i];
        atomicAdd(&g_rd[b], s);
    }
}

// ---------------- upd1 ----------------
__global__ void k_upd1(float2* __restrict__ x){
    __shared__ float red[8];
    int b = blockIdx.y;
    int idx = b*HWc + blockIdx.x*256 + threadIdx.x;
    float alpha = g_rd[b] / (g_pAp[b] + EPSf);
    float2 pv = g_p[idx];
    float2 xv = x[idx];
    x[idx] = make_float2(fmaf(alpha, pv.x, xv.x), fmaf(alpha, pv.y, xv.y));
    float2 rv = g_r[idx];
    float2 ap = g_Ap[idx];
    rv = make_float2(fmaf(-alpha, ap.x, rv.x), fmaf(-alpha, ap.y, rv.y));
    g_r[idx] = rv;
    float part = fmaf(rv.x, rv.x, rv.y*rv.y);
    #pragma unroll
    for (int off = 16; off > 0; off >>= 1) part += __shfl_down_sync(0xffffffffu, part, off);
    if ((threadIdx.x & 31) == 0) red[threadIdx.x >> 5] = part;
    __syncthreads();
    if (threadIdx.x == 0){
        float s = 0.f;
        #pragma unroll
        for (int i = 0; i < 8; i++) s += red[i];
        atomicAdd(&g_rdnew[b], s);
    }
}

// ---------------- pre ----------------
__global__ void k_pre(int copyrd){
    if (threadIdx.x < Bn){
        if (copyrd) g_rd[threadIdx.x] = g_rdnew[threadIdx.x];
        g_pAp[threadIdx.x]  = 0.f;
        g_rdnew[threadIdx.x] = 0.f;
    }
}

// ---------------- launch ----------------
extern "C" void kernel_launch(void* const* d_in, const int* in_sizes, int n_in,
                              void* d_out, int out_size){
    const float2* x    = (const float2*)d_in[0];
    const float2* adj  = (const float2*)d_in[1];
    const float2* maps = (const float2*)d_in[2];
    const float*  mask = (const float*)d_in[3];
    float2* xout = (float2*)d_out;

    dim3 gElem(HWc/256, Bn);
    dim3 gRow(Hn/8, Bn);
    dim3 gCol(Wn/8, Cn, Bn);

    k_init<<<gElem, 256>>>(x, adj, xout);

    k_fwd<false><<<gRow, 256>>>(maps);
    k_col<<<gCol, 256>>>(mask);
    k_inv<<<gRow, 256>>>(maps);
    k_r0<<<gElem, 256>>>(xout);

    for (int it = 0; it < 10; ++it){
        if (it) k_fwd<true><<<gRow, 256>>>(maps);
        else    k_fwd<false><<<gRow, 256>>>(maps);
        k_pre<<<1, 32>>>(it > 0);
        k_col<<<gCol, 256>>>(mask);
        k_inv<<<gRow, 256>>>(maps);
        k_upd1<<<gElem, 256>>>(xout);
    }
}